// round 17
// baseline (speedup 1.0000x reference)
#include <cuda_runtime.h>
#include <cstddef>

// Problem constants (fixed by the reference):
//   B_PAIRS=2048 pairs, each pair = 44 ligand nodes + 300 protein nodes (stride 344)
//   Only the ligand segment sums (even segments) feed the MLP.
//   MLP: 128 ->256 relu -> 128 relu -> 64 relu -> 1
#define B_PAIRS 2048
#define LIG     44
#define STRIDE  344
#define F_IN    128
#define N0      256
#define N1      128
#define N2      64
#define RTILE   4          // pairs per MLP block -> grid 512
#define THREADS 256

typedef unsigned long long u64;

// 1 MB scratch for the per-pair feature sums.
__device__ float g_xs[B_PAIRS * F_IN];

// ---------------- packed fp32x2 helpers (sm_103a FFMA2) --------------------
#define PACK_F32X2(d, lo, hi) \
    asm("mov.b64 %0, {%1, %2};" : "=l"(d) : "f"(lo), "f"(hi))
#define UNPACK_F32X2(lo, hi, v) \
    asm("mov.b64 {%0, %1}, %2;" : "=f"(lo), "=f"(hi) : "l"(v))
#define FMA_F32X2(d, a, b, c) \
    asm("fma.rn.f32x2 %0, %1, %2, %3;" : "=l"(d) : "l"(a), "l"(b), "l"(c))
#define ADD_F32X2(d, a, b) \
    asm("add.rn.f32x2 %0, %1, %2;" : "=l"(d) : "l"(a), "l"(b))

// ============================================================================
// Kernel A: ligand segment sum. One block per pair (46 MB hot-set stays
// L2-resident across graph replays; runs at the LTS cap ~4.3 us).
// ============================================================================
__global__ void __launch_bounds__(THREADS)
seg_sum_kernel(const float* __restrict__ features)
{
    __shared__ float4 part[8][32];
    const int tid  = threadIdx.x;
    const int pair = blockIdx.x;
    const int c4   = tid & 31;
    const int g    = tid >> 5;

    const float4* src = reinterpret_cast<const float4*>(features)
                      + (size_t)pair * STRIDE * (F_IN / 4) + c4;
    float4 acc = make_float4(0.f, 0.f, 0.f, 0.f);
#pragma unroll
    for (int r = g; r < LIG; r += 8) {
        float4 v = src[(size_t)r * (F_IN / 4)];
        acc.x += v.x; acc.y += v.y; acc.z += v.z; acc.w += v.w;
    }
    part[g][c4] = acc;
    __syncthreads();

    if (tid < 32) {
        float4 s = part[0][tid];
#pragma unroll
        for (int gg = 1; gg < 8; ++gg) {
            float4 v = part[gg][tid];
            s.x += v.x; s.y += v.y; s.z += v.z; s.w += v.w;
        }
        reinterpret_cast<float4*>(g_xs)[pair * (F_IN / 4) + tid] = s;
    }
}

// ============================================================================
// Kernel B: 4-layer MLP, RTILE=4, grid=512, 256 threads, depth-4 weight
// prefetch ring. Job shape: 1 column-pair (LDG.64) x 4 rows (one LDS.128 =
// both row-pairs) -> 4 u64 accumulators. Prefetch covers L2-hit latency
// (L1D is flushed per launch, so replays always source weights from L2).
// ============================================================================
__global__ void __launch_bounds__(THREADS)
mlp_kernel(const float* __restrict__ W0, const float* __restrict__ b0,
           const float* __restrict__ W1, const float* __restrict__ b1,
           const float* __restrict__ W2, const float* __restrict__ b2,
           const float* __restrict__ Wout, const float* __restrict__ bout,
           float* __restrict__ out)
{
    __shared__ __align__(16) u64  xsP[F_IN][RTILE / 2];  // 2 KB raw row-pairs
    __shared__ __align__(16) u64  h0P[N0][RTILE / 2];    // 4 KB
    __shared__ __align__(16) u64  h1P[N1][RTILE / 2];    // 2 KB
    __shared__ __align__(16) float h2T[N2][RTILE];       // 1 KB
    __shared__ __align__(16) u64  pbuf[7 * 32 * 4];      // 7 KB partials

    const int tid = threadIdx.x;
    const int p0  = blockIdx.x * RTILE;

    // Load 4 summed rows. Raw layout: xsP[k][rp] viewed as float[k][4].
    if (tid < 128) {
        const int pp = tid & 3;
        const int c4 = tid >> 2;                 // 0..31
        float4 v = reinterpret_cast<const float4*>(g_xs)
                       [(size_t)(p0 + pp) * (F_IN / 4) + c4];
        float* xf = reinterpret_cast<float*>(&xsP[0][0]);
        xf[(c4 * 4 + 0) * RTILE + pp] = v.x;
        xf[(c4 * 4 + 1) * RTILE + pp] = v.y;
        xf[(c4 * 4 + 2) * RTILE + pp] = v.z;
        xf[(c4 * 4 + 3) * RTILE + pp] = v.w;
    }
    __syncthreads();

    // ======== Layer 0: [4,128]@[128,256]+b relu | 128 cp x 2 kq x 64 ========
    {
        const int ct = tid & 127;                // colpair: cols 2ct, 2ct+1
        const int kq = tid >> 7;                 // 0/1, 64 k each
        u64 acc[4];                              // [col][row-pair]
#pragma unroll
        for (int i = 0; i < 4; ++i) acc[i] = 0ull;
        const float* Wp = W0 + (size_t)(kq * 64) * N0 + 2 * ct;

        float2 wr[4];
#pragma unroll
        for (int i = 0; i < 4; ++i)
            wr[i] = *reinterpret_cast<const float2*>(Wp + (size_t)i * N0);

#pragma unroll 8
        for (int kk = 0; kk < 64; ++kk) {
            float2 wv = wr[kk & 3];
            if (kk + 4 < 64)
                wr[kk & 3] = *reinterpret_cast<const float2*>(
                                 Wp + (size_t)(kk + 4) * N0);
            u64 wd0, wd1;
            PACK_F32X2(wd0, wv.x, wv.x);
            PACK_F32X2(wd1, wv.y, wv.y);
            ulonglong2 a = *reinterpret_cast<const ulonglong2*>(
                               &xsP[kq * 64 + kk][0]);
            FMA_F32X2(acc[0], a.x, wd0, acc[0]);
            FMA_F32X2(acc[1], a.y, wd0, acc[1]);
            FMA_F32X2(acc[2], a.x, wd1, acc[2]);
            FMA_F32X2(acc[3], a.y, wd1, acc[3]);
        }
        if (kq == 1) {
            u64* dst = &pbuf[ct * 4];
            *reinterpret_cast<ulonglong2*>(dst)     = make_ulonglong2(acc[0], acc[1]);
            *reinterpret_cast<ulonglong2*>(dst + 2) = make_ulonglong2(acc[2], acc[3]);
        }
        __syncthreads();
        if (kq == 0) {
            const u64* q = &pbuf[ct * 4];
            ulonglong2 q0 = *reinterpret_cast<const ulonglong2*>(q);
            ulonglong2 q1 = *reinterpret_cast<const ulonglong2*>(q + 2);
            ADD_F32X2(acc[0], acc[0], q0.x);
            ADD_F32X2(acc[1], acc[1], q0.y);
            ADD_F32X2(acc[2], acc[2], q1.x);
            ADD_F32X2(acc[3], acc[3], q1.y);
            float2 bv = *reinterpret_cast<const float2*>(b0 + 2 * ct);
            u64 bb0, bb1;
            PACK_F32X2(bb0, bv.x, bv.x);
            PACK_F32X2(bb1, bv.y, bv.y);
#pragma unroll
            for (int i = 0; i < 4; ++i) {
                ADD_F32X2(acc[i], acc[i], (i < 2) ? bb0 : bb1);
                float v0, v1; UNPACK_F32X2(v0, v1, acc[i]);
                PACK_F32X2(acc[i], fmaxf(v0, 0.f), fmaxf(v1, 0.f));
            }
            *reinterpret_cast<ulonglong2*>(&h0P[2 * ct][0]) =
                make_ulonglong2(acc[0], acc[1]);
            *reinterpret_cast<ulonglong2*>(&h0P[2 * ct + 1][0]) =
                make_ulonglong2(acc[2], acc[3]);
        }
    }
    __syncthreads();

    // ======== Layer 1: [4,256]@[256,128]+b relu | 64 cp x 4 kq x 64 =========
    {
        const int ct = tid & 63;
        const int kq = tid >> 6;                 // 0..3, 64 k each
        u64 acc[4];
#pragma unroll
        for (int i = 0; i < 4; ++i) acc[i] = 0ull;
        const float* Wp = W1 + (size_t)(kq * 64) * N1 + 2 * ct;

        float2 wr[4];
#pragma unroll
        for (int i = 0; i < 4; ++i)
            wr[i] = *reinterpret_cast<const float2*>(Wp + (size_t)i * N1);

#pragma unroll 8
        for (int kk = 0; kk < 64; ++kk) {
            float2 wv = wr[kk & 3];
            if (kk + 4 < 64)
                wr[kk & 3] = *reinterpret_cast<const float2*>(
                                 Wp + (size_t)(kk + 4) * N1);
            u64 wd0, wd1;
            PACK_F32X2(wd0, wv.x, wv.x);
            PACK_F32X2(wd1, wv.y, wv.y);
            ulonglong2 a = *reinterpret_cast<const ulonglong2*>(
                               &h0P[kq * 64 + kk][0]);
            FMA_F32X2(acc[0], a.x, wd0, acc[0]);
            FMA_F32X2(acc[1], a.y, wd0, acc[1]);
            FMA_F32X2(acc[2], a.x, wd1, acc[2]);
            FMA_F32X2(acc[3], a.y, wd1, acc[3]);
        }
        if (kq > 0) {
            u64* dst = &pbuf[((kq - 1) * 64 + ct) * 4];
            *reinterpret_cast<ulonglong2*>(dst)     = make_ulonglong2(acc[0], acc[1]);
            *reinterpret_cast<ulonglong2*>(dst + 2) = make_ulonglong2(acc[2], acc[3]);
        }
        __syncthreads();
        if (kq == 0) {
#pragma unroll
            for (int t = 0; t < 3; ++t) {
                const u64* q = &pbuf[(t * 64 + ct) * 4];
                ulonglong2 q0 = *reinterpret_cast<const ulonglong2*>(q);
                ulonglong2 q1 = *reinterpret_cast<const ulonglong2*>(q + 2);
                ADD_F32X2(acc[0], acc[0], q0.x);
                ADD_F32X2(acc[1], acc[1], q0.y);
                ADD_F32X2(acc[2], acc[2], q1.x);
                ADD_F32X2(acc[3], acc[3], q1.y);
            }
            float2 bv = *reinterpret_cast<const float2*>(b1 + 2 * ct);
            u64 bb0, bb1;
            PACK_F32X2(bb0, bv.x, bv.x);
            PACK_F32X2(bb1, bv.y, bv.y);
#pragma unroll
            for (int i = 0; i < 4; ++i) {
                ADD_F32X2(acc[i], acc[i], (i < 2) ? bb0 : bb1);
                float v0, v1; UNPACK_F32X2(v0, v1, acc[i]);
                PACK_F32X2(acc[i], fmaxf(v0, 0.f), fmaxf(v1, 0.f));
            }
            *reinterpret_cast<ulonglong2*>(&h1P[2 * ct][0]) =
                make_ulonglong2(acc[0], acc[1]);
            *reinterpret_cast<ulonglong2*>(&h1P[2 * ct + 1][0]) =
                make_ulonglong2(acc[2], acc[3]);
        }
    }
    __syncthreads();

    // ======== Layer 2: [4,128]@[128,64]+b relu | 32 cp x 8 kq x 16 ==========
    {
        const int ct = tid & 31;
        const int kq = tid >> 5;                 // 0..7, 16 k each
        u64 acc[4];
#pragma unroll
        for (int i = 0; i < 4; ++i) acc[i] = 0ull;
        const float* Wp = W2 + (size_t)(kq * 16) * N2 + 2 * ct;

        float2 wr[4];
#pragma unroll
        for (int i = 0; i < 4; ++i)
            wr[i] = *reinterpret_cast<const float2*>(Wp + (size_t)i * N2);

#pragma unroll
        for (int kk = 0; kk < 16; ++kk) {
            float2 wv = wr[kk & 3];
            if (kk + 4 < 16)
                wr[kk & 3] = *reinterpret_cast<const float2*>(
                                 Wp + (size_t)(kk + 4) * N2);
            u64 wd0, wd1;
            PACK_F32X2(wd0, wv.x, wv.x);
            PACK_F32X2(wd1, wv.y, wv.y);
            ulonglong2 a = *reinterpret_cast<const ulonglong2*>(
                               &h1P[kq * 16 + kk][0]);
            FMA_F32X2(acc[0], a.x, wd0, acc[0]);
            FMA_F32X2(acc[1], a.y, wd0, acc[1]);
            FMA_F32X2(acc[2], a.x, wd1, acc[2]);
            FMA_F32X2(acc[3], a.y, wd1, acc[3]);
        }
        if (kq > 0) {
            u64* dst = &pbuf[((kq - 1) * 32 + ct) * 4];
            *reinterpret_cast<ulonglong2*>(dst)     = make_ulonglong2(acc[0], acc[1]);
            *reinterpret_cast<ulonglong2*>(dst + 2) = make_ulonglong2(acc[2], acc[3]);
        }
        __syncthreads();
        if (kq == 0) {
#pragma unroll
            for (int t = 0; t < 7; ++t) {
                const u64* q = &pbuf[(t * 32 + ct) * 4];
                ulonglong2 q0 = *reinterpret_cast<const ulonglong2*>(q);
                ulonglong2 q1 = *reinterpret_cast<const ulonglong2*>(q + 2);
                ADD_F32X2(acc[0], acc[0], q0.x);
                ADD_F32X2(acc[1], acc[1], q0.y);
                ADD_F32X2(acc[2], acc[2], q1.x);
                ADD_F32X2(acc[3], acc[3], q1.y);
            }
            float2 bv = *reinterpret_cast<const float2*>(b2 + 2 * ct);
            u64 bb0, bb1;
            PACK_F32X2(bb0, bv.x, bv.x);
            PACK_F32X2(bb1, bv.y, bv.y);
#pragma unroll
            for (int i = 0; i < 4; ++i) {
                ADD_F32X2(acc[i], acc[i], (i < 2) ? bb0 : bb1);
                float v0, v1; UNPACK_F32X2(v0, v1, acc[i]);
                const int c  = 2 * ct + (i >> 1);
                const int rp = i & 1;
                h2T[c][2 * rp    ] = fmaxf(v0, 0.f);
                h2T[c][2 * rp + 1] = fmaxf(v1, 0.f);
            }
        }
    }
    __syncthreads();

    // ======== Output: [4,64]@[64,1]+b  (first 4 warps = 4 rows) =============
    {
        const int warp = tid >> 5;
        const int lane = tid & 31;
        if (warp < RTILE) {
            float s = h2T[2 * lane][warp]     * Wout[2 * lane]
                    + h2T[2 * lane + 1][warp] * Wout[2 * lane + 1];
#pragma unroll
            for (int o = 16; o > 0; o >>= 1)
                s += __shfl_down_sync(0xffffffffu, s, o);
            if (lane == 0)
                out[p0 + warp] = s + bout[0];
        }
    }
}

// d_in order (metadata): [0] batch_num_nodes (unused), [1] features,
// [2] W0, [3] b0, [4] W1, [5] b1, [6] W2, [7] b2, [8] Wout, [9] bout.
extern "C" void kernel_launch(void* const* d_in, const int* in_sizes, int n_in,
                              void* d_out, int out_size)
{
    const float* features = (const float*)d_in[1];
    const float* W0   = (const float*)d_in[2];
    const float* b0   = (const float*)d_in[3];
    const float* W1   = (const float*)d_in[4];
    const float* b1   = (const float*)d_in[5];
    const float* W2   = (const float*)d_in[6];
    const float* b2   = (const float*)d_in[7];
    const float* Wout = (const float*)d_in[8];
    const float* bout = (const float*)d_in[9];
    float* out = (float*)d_out;

    seg_sum_kernel<<<B_PAIRS, THREADS>>>(features);
    mlp_kernel<<<B_PAIRS / RTILE, THREADS>>>(W0, b0, W1, b1, W2, b2,
                                             Wout, bout, out);
}